// round 4
// baseline (speedup 1.0000x reference)
#include <cuda_runtime.h>

// Problem constants
#define N_B    64
#define T_T    2048
#define IN_P   8
#define C_C    2
#define M_M    10
#define NSTEP  2047            // number of increments (T-1), t in [0, 2046]
#define LSEG   8               // steps per segment
#define SSEG   256             // segments per chain (256*8 = 2048 >= 2047)
#define NCHAIN 128             // N*C
#define NU1    (NCHAIN * SSEG) // 32768 segment units
#define GRP    16
#define NU2    (NCHAIN * (SSEG / GRP)) // 2048
#define NU3    NCHAIN                  // 128
#define DH     10              // Horner (Taylor) degree for expm

// Scratch (static device arrays; allocation-free)
__device__ float g_part1[NU1 * 100]; // [unit][col][row], col-major per matrix
__device__ float g_part2[NU2 * 100];

__constant__ float c_rk[11] = {
    0.f, 1.f, 0.5f, 0.33333333333333f, 0.25f, 0.2f, 0.16666666666667f,
    0.14285714285714f, 0.125f, 0.11111111111111f, 0.1f
};

// Distributed 10x10 matmul: acc = C @ G
// 5 lanes per matrix; lane owns columns {2q, 2q+1} of every matrix.
// C columns come from lanes of the group via shuffle; G columns are local regs.
__device__ __forceinline__ void mm10(const float Cm[2][10], const float Gm[2][10],
                                     int g5, float acc[2][10])
{
#pragma unroll
    for (int j = 0; j < 2; ++j)
#pragma unroll
        for (int r = 0; r < 10; ++r) acc[j][r] = 0.f;
#pragma unroll
    for (int m = 0; m < 10; ++m) {
        int src = g5 + (m >> 1);
        float cv[10];
#pragma unroll
        for (int r = 0; r < 10; ++r)
            cv[r] = __shfl_sync(0xFFFFFFFFu, Cm[m & 1][r], src);
#pragma unroll
        for (int j = 0; j < 2; ++j) {
            float gv = Gm[j][m];
#pragma unroll
            for (int r = 0; r < 10; ++r)
                acc[j][r] = fmaf(cv[r], gv, acc[j][r]);
        }
    }
}

// Kernel 1: per-(chain,segment) ordered product of expm(G_t) over LSEG steps.
__global__ void __launch_bounds__(256, 2)
seg_kernel(const float* __restrict__ x, const float* __restrict__ A)
{
    // skew in shared, layout [i][m][c][j] so simultaneous lane reads hit
    // 20 consecutive floats (conflict-free / broadcast).
    __shared__ float sk[IN_P * M_M * C_C * M_M]; // 1600 floats
    for (int idx = threadIdx.x; idx < C_C * IN_P * M_M * M_M; idx += blockDim.x) {
        int j = idx % M_M;
        int m = (idx / M_M) % M_M;
        int i = (idx / (M_M * M_M)) % IN_P;
        int c = idx / (M_M * M_M * IN_P);
        float v = A[((c * IN_P + i) * M_M + m) * M_M + j]
                - A[((c * IN_P + i) * M_M + j) * M_M + m];
        sk[((i * M_M + m) * C_C + c) * M_M + j] = v;
    }
    __syncthreads();

    int lane = threadIdx.x & 31;
    int warp = (blockIdx.x * blockDim.x + threadIdx.x) >> 5;
    int g = lane / 5; if (g > 5) g = 5;      // lanes 30,31 shadow group 5
    int q = lane - g * 5; if (q > 4) q = 4;  // and duplicate cols 8,9 (never stored)
    int g5 = g * 5;
    int unitRaw = warp * 6 + g;
    int unit = (unitRaw < NU1) ? unitRaw : (NU1 - 1);
    bool active = (lane < 30) && (unitRaw < NU1);
    int chain = unit / SSEG;
    int seg   = unit % SSEG;
    int n = chain >> 1;
    int c = chain & 1;
    int j0 = q * 2;

    const float4* X4 = (const float4*)x;
    int t0 = seg * LSEG;
    int rb = (n * T_T + t0) * 2;
    float4 xa = X4[rb], xb = X4[rb + 1];

    float P[2][10];
#pragma unroll
    for (int j = 0; j < 2; ++j)
#pragma unroll
        for (int r = 0; r < 10; ++r) P[j][r] = (r == j0 + j) ? 1.f : 0.f;

#pragma unroll 1
    for (int s = 0; s < LSEG; ++s) {
        int t = t0 + s;
        int tn = (t < NSTEP) ? (t + 1) : t; // tail: tn==t -> dx=0 -> E=I
        int rn = (n * T_T + tn) * 2;
        float4 ya = X4[rn], yb = X4[rn + 1];
        float dx[8];
        dx[0] = ya.x - xa.x; dx[1] = ya.y - xa.y; dx[2] = ya.z - xa.z; dx[3] = ya.w - xa.w;
        dx[4] = yb.x - xb.x; dx[5] = yb.y - xb.y; dx[6] = yb.z - xb.z; dx[7] = yb.w - xb.w;
        xa = ya; xb = yb;

        // G columns (lane's 2 cols): G[row=m][col=j0+j] = sum_i dx[i]*skew[c][i][m][j0+j]
        float G[2][10];
#pragma unroll
        for (int j = 0; j < 2; ++j) {
#pragma unroll
            for (int m = 0; m < 10; ++m) G[j][m] = 0.f;
#pragma unroll
            for (int i = 0; i < 8; ++i) {
                float d = dx[i];
#pragma unroll
                for (int m = 0; m < 10; ++m)
                    G[j][m] = fmaf(d, sk[((i * M_M + m) * C_C + c) * M_M + j0 + j], G[j][m]);
            }
        }

        // P <- P * exp(G), folded Horner: C = P + (C@G)/k, k = DH..1
        float Cw[2][10];
#pragma unroll
        for (int j = 0; j < 2; ++j)
#pragma unroll
            for (int r = 0; r < 10; ++r) Cw[j][r] = P[j][r];

#pragma unroll 1
        for (int k = DH; k >= 1; --k) {
            float acc[2][10];
            mm10(Cw, G, g5, acc);
            float rk = c_rk[k];
#pragma unroll
            for (int j = 0; j < 2; ++j)
#pragma unroll
                for (int r = 0; r < 10; ++r)
                    Cw[j][r] = fmaf(acc[j][r], rk, P[j][r]);
        }
#pragma unroll
        for (int j = 0; j < 2; ++j)
#pragma unroll
            for (int r = 0; r < 10; ++r) P[j][r] = Cw[j][r];
    }

    if (active) {
        float* dst = g_part1 + unit * 100 + j0 * 10;
#pragma unroll
        for (int j = 0; j < 2; ++j)
#pragma unroll
            for (int r = 0; r < 10; ++r) dst[j * 10 + r] = P[j][r];
    }
}

// Combine kernel: ordered product of GRP consecutive partials.
// mode 0: g_part1 -> g_part2 ; mode 1: g_part2 -> out (row-major store)
__global__ void __launch_bounds__(256)
comb_kernel(int nUnits, int mode, float* __restrict__ out)
{
    const float* src = (mode == 0) ? g_part1 : g_part2;
    int lane = threadIdx.x & 31;
    int warp = (blockIdx.x * blockDim.x + threadIdx.x) >> 5;
    int g = lane / 5; if (g > 5) g = 5;
    int q = lane - g * 5; if (q > 4) q = 4;
    int g5 = g * 5;
    int unitRaw = warp * 6 + g;
    int unit = (unitRaw < nUnits) ? unitRaw : (nUnits - 1);
    bool active = (lane < 30) && (unitRaw < nUnits);
    int j0 = q * 2;

    const float* base = src + unit * (GRP * 100);
    float P[2][10];
#pragma unroll
    for (int j = 0; j < 2; ++j)
#pragma unroll
        for (int r = 0; r < 10; ++r)
            P[j][r] = base[(j0 + j) * 10 + r];

#pragma unroll 1
    for (int e = 1; e < GRP; ++e) {
        const float* eb = base + e * 100;
        float E[2][10];
#pragma unroll
        for (int j = 0; j < 2; ++j)
#pragma unroll
            for (int r = 0; r < 10; ++r)
                E[j][r] = eb[(j0 + j) * 10 + r];
        float acc[2][10];
        mm10(P, E, g5, acc);
#pragma unroll
        for (int j = 0; j < 2; ++j)
#pragma unroll
            for (int r = 0; r < 10; ++r) P[j][r] = acc[j][r];
    }

    if (active) {
        if (mode == 0) {
            float* dst = g_part2 + unit * 100 + j0 * 10;
#pragma unroll
            for (int j = 0; j < 2; ++j)
#pragma unroll
                for (int r = 0; r < 10; ++r) dst[j * 10 + r] = P[j][r];
        } else {
            float* dst = out + unit * 100; // unit == chain = n*C + c
#pragma unroll
            for (int j = 0; j < 2; ++j)
#pragma unroll
                for (int r = 0; r < 10; ++r) dst[r * 10 + (j0 + j)] = P[j][r];
        }
    }
}

extern "C" void kernel_launch(void* const* d_in, const int* in_sizes, int n_in,
                              void* d_out, int out_size)
{
    const float* x = (const float*)d_in[0];
    const float* A = (const float*)d_in[1];
    if (n_in >= 2 && in_sizes[0] == C_C * IN_P * M_M * M_M) { // defensive order check
        x = (const float*)d_in[1];
        A = (const float*)d_in[0];
    }
    float* out = (float*)d_out;

    // 256 threads = 8 warps = 48 units per block
    int b1 = (NU1 + 47) / 48;
    seg_kernel<<<b1, 256>>>(x, A);
    int b2 = (NU2 + 47) / 48;
    comb_kernel<<<b2, 256>>>(NU2, 0, out);
    int b3 = (NU3 + 47) / 48;
    comb_kernel<<<b3, 256>>>(NU3, 1, out);
}